// round 1
// baseline (speedup 1.0000x reference)
#include <cuda_runtime.h>

// out[h1,w1,c1,h2,w2,c2] = g^(|dh|+|dw|+|dc|) * (1 + spec_pe[c1,c2]*mean[h1,w1,c1]) * decay[c1]
// mean[h1,w1,c1] = Sh[h1]*Sw[w1]*Sc[c1] / (H*W*C), separable geometric sums.
// H=W=32, C=8. Output: 1024 * 65536 floats = 268.4 MB, write-bound.

#define GAMMA 0.9f

__global__ __launch_bounds__(256) void mrp3d_kernel(const float* __restrict__ decay,
                                                    const float* __restrict__ spec_pe,
                                                    float* __restrict__ out) {
    __shared__ float sPow[40];    // gamma^d, d = 0..39 (max needed: 31)
    __shared__ float4 sCoef[16];  // fused coef [c1][c2-half]: decay*(1+spec*mean)*g^|c1-c2|

    const int h1 = blockIdx.x >> 5;
    const int w1 = blockIdx.x & 31;
    const int t  = threadIdx.x;

    // Build gamma^d table (iterative product; <70 ulp error, fine for 1e-3 tol)
    if (t < 40) {
        float p = 1.0f;
        for (int i = 0; i < t; ++i) p *= GAMMA;
        sPow[t] = p;
    }
    __syncthreads();

    // Build fused 8x8 coefficient table for this (h1,w1)
    if (t < 64) {
        const int c1 = t >> 3;
        const int c2 = t & 7;
        float Sh = 0.0f, Sw = 0.0f, Sc = 0.0f;
        #pragma unroll
        for (int j = 0; j < 32; ++j) {
            Sh += sPow[abs(h1 - j)];
            Sw += sPow[abs(w1 - j)];
        }
        #pragma unroll
        for (int j = 0; j < 8; ++j) Sc += sPow[abs(c1 - j)];
        const float mean = Sh * Sw * Sc * (1.0f / 8192.0f);
        const float coef = decay[c1] * (1.0f + spec_pe[c1 * 8 + c2] * mean) * sPow[abs(c1 - c2)];
        reinterpret_cast<float*>(sCoef)[t] = coef;
    }
    __syncthreads();

    // Output slice for this (h1,w1): 65536 floats = 16384 float4, contiguous.
    float4* __restrict__ outv = reinterpret_cast<float4*>(out) + (size_t)blockIdx.x * 16384;

    // float4 index within c1-slice: r = (h2*32 + w2)*2 + half, r in [0,2048)
    // Thread-invariant pieces: half = t&1, w2 = (t>>1)&31, h2 base = t>>6 (steps of 4).
    const int half    = t & 1;
    const int w2      = (t >> 1) & 31;
    const int h2base  = t >> 6;
    const float sW    = sPow[abs(w1 - w2)];

    #pragma unroll
    for (int c1 = 0; c1 < 8; ++c1) {
        const float4 cf = sCoef[(c1 << 1) | half];
        float4* outc = outv + c1 * 2048;
        #pragma unroll
        for (int it = 0; it < 8; ++it) {
            const int h2 = h2base + (it << 2);
            const int r  = t + (it << 8);
            const float s = sPow[abs(h1 - h2)] * sW;
            float4 o;
            o.x = s * cf.x;
            o.y = s * cf.y;
            o.z = s * cf.z;
            o.w = s * cf.w;
            outc[r] = o;
        }
    }
}

extern "C" void kernel_launch(void* const* d_in, const int* in_sizes, int n_in,
                              void* d_out, int out_size) {
    // Inputs (per setup_inputs order): x (unused, 524288), decay (8), spec_pe (64).
    // Identify by element count to be robust to ordering.
    const float* decay   = nullptr;
    const float* spec_pe = nullptr;
    for (int i = 0; i < n_in; ++i) {
        if (in_sizes[i] == 8)       decay   = (const float*)d_in[i];
        else if (in_sizes[i] == 64) spec_pe = (const float*)d_in[i];
    }
    mrp3d_kernel<<<1024, 256>>>(decay, spec_pe, (float*)d_out);
}